// round 1
// baseline (speedup 1.0000x reference)
#include <cuda_runtime.h>
#include <math.h>

#define N_TOK 4096
#define DIM   128
#define NH    8
#define HD    (NH*DIM)   // 1024

// Scratch (static device globals -- no allocation allowed)
__device__ __align__(128) float g_qT  [(size_t)NH * DIM * N_TOK];  // [h][d][n]
__device__ __align__(128) float g_k   [(size_t)NH * N_TOK * DIM];  // [h][n][d]
__device__ __align__(128) float g_vT  [(size_t)NH * DIM * N_TOK];  // [h][d][n]
__device__ __align__(128) float g_attn[(size_t)N_TOK * HD];        // [n][h*128+d]

// ---------------------------------------------------------------------------
// Generic tiled SGEMM + bias:  C = A[M,K] @ B[K,Nn] + bias[Nn]
// Per-z offsets on B/bias/C (batched over heads).
// transC: store C transposed (C[col*M + row]) -- used to produce qT / vT.
// srcSel: 0 -> Aext, 1 -> g_attn.   dstSel: 0 g_qT, 1 g_k, 2 g_vT, 3 Cext.
// BM=BN=64, BK=16, 256 threads, 4x4 per thread.
// ---------------------------------------------------------------------------
__global__ __launch_bounds__(256) void sgemm_bias_kernel(
    const float* __restrict__ Aext, const float* __restrict__ Bmat,
    const float* __restrict__ bias, float* __restrict__ Cext,
    int M, int Nn, int K, long sB, long sBias, long sC,
    int transC, int srcSel, int dstSel)
{
    __shared__ float As[16][68];
    __shared__ float Bs[16][68];

    const float* A = (srcSel == 0) ? Aext : g_attn;
    float* C;
    switch (dstSel) {
        case 0:  C = g_qT; break;
        case 1:  C = g_k;  break;
        case 2:  C = g_vT; break;
        default: C = Cext; break;
    }

    int z = blockIdx.z;
    const float* B  = Bmat + (long)z * sB;
    const float* bb = bias + (long)z * sBias;
    C += (long)z * sC;

    int row0 = blockIdx.y * 64;
    int col0 = blockIdx.x * 64;
    int tid  = threadIdx.x;
    int tx   = tid & 15, ty = tid >> 4;

    float acc[4][4] = {};
    int ai = tid >> 2, aj = tid & 3;   // A tile loader: 64 rows x 4 float4
    int bi = tid >> 4, bj = tid & 15;  // B tile loader: 16 rows x 16 float4

    for (int k0 = 0; k0 < K; k0 += 16) {
        float4 av = *(const float4*)&A[(long)(row0 + ai) * K + k0 + aj * 4];
        As[aj*4+0][ai] = av.x; As[aj*4+1][ai] = av.y;
        As[aj*4+2][ai] = av.z; As[aj*4+3][ai] = av.w;
        *(float4*)&Bs[bi][bj*4] =
            *(const float4*)&B[(long)(k0 + bi) * Nn + col0 + bj * 4];
        __syncthreads();
        #pragma unroll
        for (int kk = 0; kk < 16; ++kk) {
            float4 a = *(float4*)&As[kk][ty*4];
            float4 b = *(float4*)&Bs[kk][tx*4];
            float ar[4] = {a.x, a.y, a.z, a.w};
            float br[4] = {b.x, b.y, b.z, b.w};
            #pragma unroll
            for (int i = 0; i < 4; ++i)
                #pragma unroll
                for (int j = 0; j < 4; ++j)
                    acc[i][j] = fmaf(ar[i], br[j], acc[i][j]);
        }
        __syncthreads();
    }

    #pragma unroll
    for (int i = 0; i < 4; ++i) {
        int r = row0 + ty*4 + i;
        #pragma unroll
        for (int j = 0; j < 4; ++j) {
            int c = col0 + tx*4 + j;
            float v = acc[i][j] + bb[c];
            if (transC) C[(long)c * M + r] = v;
            else        C[(long)r * Nn + c] = v;
        }
    }
}

// ---------------------------------------------------------------------------
// Flash-style attention for scores = v @ q^T, softmax over q-index, out = P @ k.
// One block = one head x 64 "v" rows. Streams 64-wide q/k tiles over all 4096.
// smem: Vst[128][68] (transposed V tile), QKs (Q transposed [128][68], then
// K normal [64][132], sequentially reused), Ps[64][68].
// 256 threads: 16x16 grid; each thread owns 4 rows x (4+4) out cols.
// ---------------------------------------------------------------------------
__global__ __launch_bounds__(256, 2) void flash_attn_kernel()
{
    extern __shared__ float sm[];
    float* Vst = sm;                 // 128*68
    float* QKs = sm + 128*68;        // max(128*68, 64*132) = 8704
    float* Ps  = sm + 2*128*68;      // 64*68

    int h  = blockIdx.y;
    int i0 = blockIdx.x * 64;
    int tid = threadIdx.x;
    int tx = tid & 15, ty = tid >> 4;

    const float* qT = g_qT + (size_t)h * DIM * N_TOK;
    const float* vT = g_vT + (size_t)h * DIM * N_TOK;
    const float* kM = g_k  + (size_t)h * N_TOK * DIM;

    // Prologue: V tile, transposed layout Vst[d][r] (coalesced from vT)
    #pragma unroll
    for (int it = 0; it < 8; ++it) {
        int idx = tid + it * 256;            // 0..2047 float4s
        int d = idx >> 4, r4 = idx & 15;
        *(float4*)&Vst[d*68 + r4*4] =
            *(const float4*)&vT[(size_t)d * N_TOK + i0 + r4*4];
    }

    float rm[4], rl[4];
    #pragma unroll
    for (int r = 0; r < 4; ++r) { rm[r] = -INFINITY; rl[r] = 0.f; }
    float acc[4][8] = {};

    for (int j0 = 0; j0 < N_TOK; j0 += 64) {
        __syncthreads();   // QKs free (prev iter readers done); Vst visible (1st iter)
        // Load Q tile transposed: Qt[d][c] <- qT[d][j0+c]
        #pragma unroll
        for (int it = 0; it < 8; ++it) {
            int idx = tid + it * 256;
            int d = idx >> 4, c4 = idx & 15;
            *(float4*)&QKs[d*68 + c4*4] =
                *(const float4*)&qT[(size_t)d * N_TOK + j0 + c4*4];
        }
        __syncthreads();

        // S[4][4] = V rows (ty*4..) dot Q rows (tx*4..) over d=128
        float s[4][4] = {};
        #pragma unroll 4
        for (int d = 0; d < DIM; ++d) {
            float4 a = *(float4*)&Vst[d*68 + ty*4];
            float4 b = *(float4*)&QKs[d*68 + tx*4];
            float ar[4] = {a.x, a.y, a.z, a.w};
            float br[4] = {b.x, b.y, b.z, b.w};
            #pragma unroll
            for (int i = 0; i < 4; ++i)
                #pragma unroll
                for (int j = 0; j < 4; ++j)
                    s[i][j] = fmaf(ar[i], br[j], s[i][j]);
        }

        // Online softmax per owned row; 16 threads/row reduce via half-warp shfl
        #pragma unroll
        for (int r = 0; r < 4; ++r) {
            float mx = fmaxf(fmaxf(s[r][0], s[r][1]), fmaxf(s[r][2], s[r][3]));
            #pragma unroll
            for (int off = 1; off < 16; off <<= 1)
                mx = fmaxf(mx, __shfl_xor_sync(0xffffffffu, mx, off));
            float mnew  = fmaxf(rm[r], mx);
            float scale = __expf(rm[r] - mnew);
            rm[r] = mnew;
            float rs = 0.f;
            #pragma unroll
            for (int c = 0; c < 4; ++c) {
                s[r][c] = __expf(s[r][c] - mnew);
                rs += s[r][c];
            }
            #pragma unroll
            for (int off = 1; off < 16; off <<= 1)
                rs += __shfl_xor_sync(0xffffffffu, rs, off);
            rl[r] = rl[r] * scale + rs;
            #pragma unroll
            for (int j = 0; j < 8; ++j) acc[r][j] *= scale;
            *(float4*)&Ps[(ty*4 + r)*68 + tx*4] =
                make_float4(s[r][0], s[r][1], s[r][2], s[r][3]);
        }
        __syncthreads();

        // Load K tile (normal layout) into QKs as [64][132]
        #pragma unroll
        for (int it = 0; it < 8; ++it) {
            int idx = tid + it * 256;
            int c = idx >> 5, d4 = idx & 31;
            *(float4*)&QKs[c*132 + d4*4] =
                *(const float4*)&kM[(size_t)(j0 + c) * DIM + d4*4];
        }
        __syncthreads();

        // acc[4][8] += P(rows ty*4..) @ K  (cols tx*4.. and 64+tx*4..)
        #pragma unroll 4
        for (int cc = 0; cc < 64; cc += 4) {
            float4 p4[4];
            #pragma unroll
            for (int r = 0; r < 4; ++r)
                p4[r] = *(float4*)&Ps[(ty*4 + r)*68 + cc];
            #pragma unroll
            for (int u = 0; u < 4; ++u) {
                float4 b1 = *(float4*)&QKs[(cc+u)*132 + tx*4];
                float4 b2 = *(float4*)&QKs[(cc+u)*132 + 64 + tx*4];
                #pragma unroll
                for (int r = 0; r < 4; ++r) {
                    float pu[4] = {p4[r].x, p4[r].y, p4[r].z, p4[r].w};
                    float pv = pu[u];
                    acc[r][0] = fmaf(pv, b1.x, acc[r][0]);
                    acc[r][1] = fmaf(pv, b1.y, acc[r][1]);
                    acc[r][2] = fmaf(pv, b1.z, acc[r][2]);
                    acc[r][3] = fmaf(pv, b1.w, acc[r][3]);
                    acc[r][4] = fmaf(pv, b2.x, acc[r][4]);
                    acc[r][5] = fmaf(pv, b2.y, acc[r][5]);
                    acc[r][6] = fmaf(pv, b2.z, acc[r][6]);
                    acc[r][7] = fmaf(pv, b2.w, acc[r][7]);
                }
            }
        }
    }

    // Epilogue: normalize, write concat layout g_attn[n][h*128 + d]
    #pragma unroll
    for (int r = 0; r < 4; ++r) {
        float inv = 1.f / rl[r];
        size_t n = (size_t)(i0 + ty*4 + r);
        float* dst = g_attn + n * HD + (size_t)h * DIM;
        *(float4*)&dst[tx*4] = make_float4(acc[r][0]*inv, acc[r][1]*inv,
                                           acc[r][2]*inv, acc[r][3]*inv);
        *(float4*)&dst[64 + tx*4] = make_float4(acc[r][4]*inv, acc[r][5]*inv,
                                                acc[r][6]*inv, acc[r][7]*inv);
    }
}

// ---------------------------------------------------------------------------
extern "C" void kernel_launch(void* const* d_in, const int* in_sizes, int n_in,
                              void* d_out, int out_size)
{
    const float* x  = (const float*)d_in[0];
    const float* Wq = (const float*)d_in[1];
    const float* bq = (const float*)d_in[2];
    const float* Wk = (const float*)d_in[3];
    const float* bk = (const float*)d_in[4];
    const float* Wv = (const float*)d_in[5];
    const float* bv = (const float*)d_in[6];
    const float* Wo = (const float*)d_in[7];
    const float* bo = (const float*)d_in[8];
    float* out = (float*)d_out;

    const int FLASH_SMEM = (2*128*68 + 64*68) * (int)sizeof(float);  // 87040
    cudaFuncSetAttribute(flash_attn_kernel,
                         cudaFuncAttributeMaxDynamicSharedMemorySize, FLASH_SMEM);

    dim3 blk(256);
    dim3 g1(DIM/64, N_TOK/64, NH);

    // q (transposed out), k (normal), v (transposed out)
    sgemm_bias_kernel<<<g1, blk>>>(x, Wq, bq, nullptr, N_TOK, DIM, DIM,
                                   (long)DIM*DIM, DIM, (long)DIM*N_TOK, 1, 0, 0);
    sgemm_bias_kernel<<<g1, blk>>>(x, Wk, bk, nullptr, N_TOK, DIM, DIM,
                                   (long)DIM*DIM, DIM, (long)N_TOK*DIM, 0, 0, 1);
    sgemm_bias_kernel<<<g1, blk>>>(x, Wv, bv, nullptr, N_TOK, DIM, DIM,
                                   (long)DIM*DIM, DIM, (long)DIM*N_TOK, 1, 0, 2);

    dim3 g2(N_TOK/64, NH);
    flash_attn_kernel<<<g2, blk, FLASH_SMEM>>>();

    dim3 g3(DIM/64, N_TOK/64, 1);
    sgemm_bias_kernel<<<g3, blk>>>(nullptr, Wo, bo, out, N_TOK, DIM, HD,
                                   0, 0, 0, 0, 1, 3);
}

// round 4
// speedup vs baseline: 2.5914x; 2.5914x over previous
#include <cuda_runtime.h>
#include <cuda_bf16.h>
#include <math.h>
#include <stdint.h>

#define N_TOK 4096
#define DIM   128
#define NH    8
#define HD    (NH*DIM)   // 1024

// ---------------------------------------------------------------------------
// Global scratch: q,k,v as [h][n][d] bf16 hi/lo splits; attn output fp32.
// ---------------------------------------------------------------------------
__device__ __align__(128) __nv_bfloat16 g_qhi[(size_t)NH * N_TOK * DIM];
__device__ __align__(128) __nv_bfloat16 g_qlo[(size_t)NH * N_TOK * DIM];
__device__ __align__(128) __nv_bfloat16 g_khi[(size_t)NH * N_TOK * DIM];
__device__ __align__(128) __nv_bfloat16 g_klo[(size_t)NH * N_TOK * DIM];
__device__ __align__(128) __nv_bfloat16 g_vhi[(size_t)NH * N_TOK * DIM];
__device__ __align__(128) __nv_bfloat16 g_vlo[(size_t)NH * N_TOK * DIM];
__device__ __align__(128) float g_attn[(size_t)N_TOK * HD];   // [n][h*128+d]

// ---------------------------------------------------------------------------
// mma.sync / ldmatrix helpers (base-target instructions, sm_80+)
// ---------------------------------------------------------------------------
__device__ __forceinline__ uint32_t smem_u32(const void* p) {
    uint32_t a;
    asm("{ .reg .u64 t; cvta.to.shared.u64 t, %1; cvt.u32.u64 %0, t; }"
        : "=r"(a) : "l"(p));
    return a;
}
__device__ __forceinline__ void ldsm_x4(uint32_t* r, uint32_t addr) {
    asm volatile("ldmatrix.sync.aligned.m8n8.x4.shared.b16 {%0,%1,%2,%3}, [%4];"
        : "=r"(r[0]), "=r"(r[1]), "=r"(r[2]), "=r"(r[3]) : "r"(addr));
}
__device__ __forceinline__ void ldsm_x4_t(uint32_t* r, uint32_t addr) {
    asm volatile("ldmatrix.sync.aligned.m8n8.x4.trans.shared.b16 {%0,%1,%2,%3}, [%4];"
        : "=r"(r[0]), "=r"(r[1]), "=r"(r[2]), "=r"(r[3]) : "r"(addr));
}
__device__ __forceinline__ void mma_bf16(float* c, const uint32_t* a,
                                         uint32_t b0, uint32_t b1) {
    asm volatile("mma.sync.aligned.m16n8k16.row.col.f32.bf16.bf16.f32 "
        "{%0,%1,%2,%3}, {%4,%5,%6,%7}, {%8,%9}, {%0,%1,%2,%3};"
        : "+f"(c[0]), "+f"(c[1]), "+f"(c[2]), "+f"(c[3])
        : "r"(a[0]), "r"(a[1]), "r"(a[2]), "r"(a[3]), "r"(b0), "r"(b1));
}
__device__ __forceinline__ uint32_t pack2bf(float a, float b) {
    unsigned short ua = __bfloat16_as_ushort(__float2bfloat16(a));
    unsigned short ub = __bfloat16_as_ushort(__float2bfloat16(b));
    return (uint32_t)ua | ((uint32_t)ub << 16);
}

// ---------------------------------------------------------------------------
// SGEMM + bias for projections / output.
// dstSel: 0 -> q split, 1 -> k split, 2 -> v split, 3 -> fp32 Cext
// ---------------------------------------------------------------------------
__global__ __launch_bounds__(256) void sgemm_bias_kernel(
    const float* __restrict__ Aext, const float* __restrict__ Bmat,
    const float* __restrict__ bias, float* __restrict__ Cext,
    int M, int Nn, int K, long sB, long sBias, int srcSel, int dstSel)
{
    __shared__ float As[16][68];
    __shared__ float Bs[16][68];

    const float* A = (srcSel == 0) ? Aext : g_attn;
    int z = blockIdx.z;
    const float* B  = Bmat + (long)z * sB;
    const float* bb = bias + (long)z * sBias;

    int row0 = blockIdx.y * 64, col0 = blockIdx.x * 64;
    int tid = threadIdx.x, tx = tid & 15, ty = tid >> 4;
    float acc[4][4] = {};
    int ai = tid >> 2, aj = tid & 3;
    int bi = tid >> 4, bj = tid & 15;

    for (int k0 = 0; k0 < K; k0 += 16) {
        float4 av = *(const float4*)&A[(long)(row0 + ai) * K + k0 + aj * 4];
        As[aj*4+0][ai] = av.x; As[aj*4+1][ai] = av.y;
        As[aj*4+2][ai] = av.z; As[aj*4+3][ai] = av.w;
        *(float4*)&Bs[bi][bj*4] = *(const float4*)&B[(long)(k0 + bi) * Nn + col0 + bj*4];
        __syncthreads();
        #pragma unroll
        for (int kk = 0; kk < 16; ++kk) {
            float4 a = *(float4*)&As[kk][ty*4];
            float4 b = *(float4*)&Bs[kk][tx*4];
            float ar[4] = {a.x,a.y,a.z,a.w}, br[4] = {b.x,b.y,b.z,b.w};
            #pragma unroll
            for (int i = 0; i < 4; ++i)
                #pragma unroll
                for (int j = 0; j < 4; ++j)
                    acc[i][j] = fmaf(ar[i], br[j], acc[i][j]);
        }
        __syncthreads();
    }

    __nv_bfloat16 *hiA = nullptr, *loA = nullptr;
    if (dstSel == 0) { hiA = g_qhi; loA = g_qlo; }
    else if (dstSel == 1) { hiA = g_khi; loA = g_klo; }
    else if (dstSel == 2) { hiA = g_vhi; loA = g_vlo; }

    #pragma unroll
    for (int i = 0; i < 4; ++i) {
        int r = row0 + ty*4 + i;
        #pragma unroll
        for (int j = 0; j < 4; ++j) {
            int c = col0 + tx*4 + j;
            float v = acc[i][j] + bb[c];
            if (dstSel == 3) {
                Cext[(long)r * Nn + c] = v;
            } else {
                long idx = (long)r * Nn + c + (long)z * N_TOK * DIM;
                __nv_bfloat16 hv = __float2bfloat16(v);
                hiA[idx] = hv;
                loA[idx] = __float2bfloat16(v - __bfloat162float(hv));
            }
        }
    }
}

// ---------------------------------------------------------------------------
// Flash attention via mma.sync (bf16 hi/lo split, fp32 accumulate).
// One CTA = one head x 128 v-rows; 8 warps x 16-row stripes.
// j-loop over 64-token q/k tiles (double buffered). P stays in registers.
// smem rows padded: 128 bf16 + 8 pad = 272 B/row (conflict-free ldmatrix).
// ---------------------------------------------------------------------------
#define ROWB   272
#define OFF_VH 0
#define OFF_VL 34816
#define OFF_Q  69632             // + buf*34816 ; QH at +0, QL at +17408
#define OFF_K  139264            // + buf*34816 ; KH at +0, KL at +17408
#define SMEM_DYN 208896

__global__ __launch_bounds__(256, 1) void attn_mma_kernel()
{
    extern __shared__ __align__(128) char sm[];
    const uint32_t sb = smem_u32(sm);

    const int tid  = threadIdx.x;
    const int warp = tid >> 5;
    const int lane = tid & 31;
    const int gid  = lane >> 2;        // group id (row within 8)
    const int tg   = lane & 3;         // thread in group (col pair)
    const int h    = blockIdx.y;
    const int i0   = blockIdx.x * 128;

    const uint4* qh = (const uint4*)g_qhi;
    const uint4* ql = (const uint4*)g_qlo;
    const uint4* kh = (const uint4*)g_khi;
    const uint4* kl = (const uint4*)g_klo;
    const uint4* vh = (const uint4*)g_vhi;
    const uint4* vl = (const uint4*)g_vlo;

    // ---- V resident tile: 128 rows x 128 bf16, hi + lo ----
    #pragma unroll
    for (int it = 0; it < 8; ++it) {
        int idx = tid + it * 256;            // 0..2047
        int row = idx >> 4, c = idx & 15;
        int so = row * ROWB + c * 16;
        size_t g = ((size_t)h * N_TOK + i0 + row) * 16 + c;
        *(uint4*)(sm + OFF_VH + so) = vh[g];
        *(uint4*)(sm + OFF_VL + so) = vl[g];
    }
    // ---- Q/K tile buffer 0 ----
    {
        char* qb = sm + OFF_Q;
        char* kb = sm + OFF_K;
        #pragma unroll
        for (int it = 0; it < 4; ++it) {
            int idx = tid + it * 256;        // 0..1023
            int row = idx >> 4, c = idx & 15;
            int so = row * ROWB + c * 16;
            size_t g = ((size_t)h * N_TOK + row) * 16 + c;
            *(uint4*)(qb + so)         = qh[g];
            *(uint4*)(qb + 17408 + so) = ql[g];
            *(uint4*)(kb + so)         = kh[g];
            *(uint4*)(kb + 17408 + so) = kl[g];
        }
    }
    __syncthreads();

    // ldmatrix lane-address components
    const int a_row = warp * 16 + (lane & 15);        // V A-frag row
    const int a_ch  = (lane >> 4) * 8;                // V A-frag col half
    const int b_tok = (lane & 7) + ((lane >> 4) & 1) * 8;   // Q B-frag token
    const int b_kh  = ((lane >> 3) & 1) * 8;                // Q B-frag k half
    const int t_kr  = (lane & 7) + ((lane >> 3) & 1) * 8;   // K(trans) k row
    const int t_nc  = ((lane >> 4) & 1) * 8;                // K(trans) n col

    float ot[16][4];
    #pragma unroll
    for (int n = 0; n < 16; ++n)
        #pragma unroll
        for (int u = 0; u < 4; ++u) ot[n][u] = 0.f;
    float m0 = -INFINITY, m1 = -INFINITY, l0 = 0.f, l1 = 0.f;

    #pragma unroll 1
    for (int j = 0; j < 64; ++j) {
        // ---- prefetch next Q/K tiles into other buffer ----
        if (j < 63) {
            int j0n = (j + 1) * 64;
            char* qb = sm + OFF_Q + ((j + 1) & 1) * 34816;
            char* kb = sm + OFF_K + ((j + 1) & 1) * 34816;
            #pragma unroll
            for (int it = 0; it < 4; ++it) {
                int idx = tid + it * 256;
                int row = idx >> 4, c = idx & 15;
                int so = row * ROWB + c * 16;
                size_t g = ((size_t)h * N_TOK + j0n + row) * 16 + c;
                *(uint4*)(qb + so)         = qh[g];
                *(uint4*)(qb + 17408 + so) = ql[g];
                *(uint4*)(kb + so)         = kh[g];
                *(uint4*)(kb + 17408 + so) = kl[g];
            }
        }

        const uint32_t qbh = sb + OFF_Q + (j & 1) * 34816;
        const uint32_t qbl = qbh + 17408;
        const uint32_t kbh = sb + OFF_K + (j & 1) * 34816;
        const uint32_t kbl = kbh + 17408;

        // ---- S = V . Q^T  (16x64 per warp), 3-term bf16 split ----
        float st[8][4];
        #pragma unroll
        for (int n = 0; n < 8; ++n)
            #pragma unroll
            for (int u = 0; u < 4; ++u) st[n][u] = 0.f;

        #pragma unroll
        for (int ks = 0; ks < 8; ++ks) {
            uint32_t avh[4], avl[4];
            uint32_t va = a_row * ROWB + (ks * 16 + a_ch) * 2;
            ldsm_x4(avh, sb + OFF_VH + va);
            ldsm_x4(avl, sb + OFF_VL + va);
            #pragma unroll
            for (int nt2 = 0; nt2 < 4; ++nt2) {
                uint32_t bqh[4], bql[4];
                uint32_t qa = (nt2 * 16 + b_tok) * ROWB + (ks * 16 + b_kh) * 2;
                ldsm_x4(bqh, qbh + qa);
                ldsm_x4(bql, qbl + qa);
                mma_bf16(st[2*nt2],   avh, bqh[0], bqh[1]);
                mma_bf16(st[2*nt2],   avh, bql[0], bql[1]);
                mma_bf16(st[2*nt2],   avl, bqh[0], bqh[1]);
                mma_bf16(st[2*nt2+1], avh, bqh[2], bqh[3]);
                mma_bf16(st[2*nt2+1], avh, bql[2], bql[3]);
                mma_bf16(st[2*nt2+1], avl, bqh[2], bqh[3]);
            }
        }

        // ---- online softmax (rows gid, gid+8 of this warp's stripe) ----
        float mx0 = st[0][0], mx1 = st[0][2];
        #pragma unroll
        for (int n = 0; n < 8; ++n) {
            mx0 = fmaxf(mx0, fmaxf(st[n][0], st[n][1]));
            mx1 = fmaxf(mx1, fmaxf(st[n][2], st[n][3]));
        }
        mx0 = fmaxf(mx0, __shfl_xor_sync(0xffffffffu, mx0, 1));
        mx0 = fmaxf(mx0, __shfl_xor_sync(0xffffffffu, mx0, 2));
        mx1 = fmaxf(mx1, __shfl_xor_sync(0xffffffffu, mx1, 1));
        mx1 = fmaxf(mx1, __shfl_xor_sync(0xffffffffu, mx1, 2));
        float mn0 = fmaxf(m0, mx0), mn1 = fmaxf(m1, mx1);
        float sc0 = __expf(m0 - mn0), sc1 = __expf(m1 - mn1);
        m0 = mn0; m1 = mn1;
        float sum0 = 0.f, sum1 = 0.f;
        #pragma unroll
        for (int n = 0; n < 8; ++n) {
            st[n][0] = __expf(st[n][0] - m0); sum0 += st[n][0];
            st[n][1] = __expf(st[n][1] - m0); sum0 += st[n][1];
            st[n][2] = __expf(st[n][2] - m1); sum1 += st[n][2];
            st[n][3] = __expf(st[n][3] - m1); sum1 += st[n][3];
        }
        sum0 += __shfl_xor_sync(0xffffffffu, sum0, 1);
        sum0 += __shfl_xor_sync(0xffffffffu, sum0, 2);
        sum1 += __shfl_xor_sync(0xffffffffu, sum1, 1);
        sum1 += __shfl_xor_sync(0xffffffffu, sum1, 2);
        l0 = l0 * sc0 + sum0;
        l1 = l1 * sc1 + sum1;

        // rescale O accumulators
        #pragma unroll
        for (int n = 0; n < 16; ++n) {
            ot[n][0] *= sc0; ot[n][1] *= sc0;
            ot[n][2] *= sc1; ot[n][3] *= sc1;
        }

        // ---- P -> bf16 hi/lo A-frags (registers only) ----
        // A-frag order: a0=(row g, k0-7) a1=(row g+8, k0-7)
        //               a2=(row g, k8-15) a3=(row g+8, k8-15)
        // st[2*ks2]   = cols ks2*16+0..7  -> {a0(v0,v1), a1(v2,v3)}
        // st[2*ks2+1] = cols ks2*16+8..15 -> {a2(v0,v1), a3(v2,v3)}
        uint32_t ph[4][4], pl[4][4];
        #pragma unroll
        for (int ks2 = 0; ks2 < 4; ++ks2) {
            #pragma unroll
            for (int half = 0; half < 2; ++half) {
                int n = 2 * ks2 + half;
                float v0 = st[n][0], v1 = st[n][1], v2 = st[n][2], v3 = st[n][3];
                __nv_bfloat16 h0 = __float2bfloat16(v0);
                __nv_bfloat16 h1 = __float2bfloat16(v1);
                __nv_bfloat16 h2 = __float2bfloat16(v2);
                __nv_bfloat16 h3 = __float2bfloat16(v3);
                ph[ks2][2*half+0] = (uint32_t)__bfloat16_as_ushort(h0)
                                  | ((uint32_t)__bfloat16_as_ushort(h1) << 16);
                ph[ks2][2*half+1] = (uint32_t)__bfloat16_as_ushort(h2)
                                  | ((uint32_t)__bfloat16_as_ushort(h3) << 16);
                pl[ks2][2*half+0] = pack2bf(v0 - __bfloat162float(h0),
                                            v1 - __bfloat162float(h1));
                pl[ks2][2*half+1] = pack2bf(v2 - __bfloat162float(h2),
                                            v3 - __bfloat162float(h3));
            }
        }
        // (no reordering needed: layout above is already {a0,a1,a2,a3})

        // ---- O += P . K  (16x128 per warp), 3-term split ----
        #pragma unroll
        for (int ks2 = 0; ks2 < 4; ++ks2) {
            #pragma unroll
            for (int ntp = 0; ntp < 8; ++ntp) {
                uint32_t bkh[4], bkl[4];
                uint32_t ka = (ks2 * 16 + t_kr) * ROWB + (ntp * 16 + t_nc) * 2;
                ldsm_x4_t(bkh, kbh + ka);
                ldsm_x4_t(bkl, kbl + ka);
                mma_bf16(ot[2*ntp],   ph[ks2], bkh[0], bkh[1]);
                mma_bf16(ot[2*ntp],   ph[ks2], bkl[0], bkl[1]);
                mma_bf16(ot[2*ntp],   pl[ks2], bkh[0], bkh[1]);
                mma_bf16(ot[2*ntp+1], ph[ks2], bkh[2], bkh[3]);
                mma_bf16(ot[2*ntp+1], ph[ks2], bkl[2], bkl[3]);
                mma_bf16(ot[2*ntp+1], pl[ks2], bkh[2], bkh[3]);
            }
        }
        __syncthreads();
    }

    // ---- epilogue: normalize, write concat layout ----
    float inv0 = 1.f / l0, inv1 = 1.f / l1;
    int r0 = i0 + warp * 16 + gid;
    int r1 = r0 + 8;
    #pragma unroll
    for (int n = 0; n < 16; ++n) {
        int col = h * 128 + n * 8 + tg * 2;
        *(float2*)&g_attn[(size_t)r0 * HD + col] =
            make_float2(ot[n][0] * inv0, ot[n][1] * inv0);
        *(float2*)&g_attn[(size_t)r1 * HD + col] =
            make_float2(ot[n][2] * inv1, ot[n][3] * inv1);
    }
}

// ---------------------------------------------------------------------------
extern "C" void kernel_launch(void* const* d_in, const int* in_sizes, int n_in,
                              void* d_out, int out_size)
{
    const float* x  = (const float*)d_in[0];
    const float* Wq = (const float*)d_in[1];
    const float* bq = (const float*)d_in[2];
    const float* Wk = (const float*)d_in[3];
    const float* bk = (const float*)d_in[4];
    const float* Wv = (const float*)d_in[5];
    const float* bv = (const float*)d_in[6];
    const float* Wo = (const float*)d_in[7];
    const float* bo = (const float*)d_in[8];
    float* out = (float*)d_out;

    cudaFuncSetAttribute(attn_mma_kernel,
                         cudaFuncAttributeMaxDynamicSharedMemorySize, SMEM_DYN);

    dim3 blk(256);
    dim3 g1(DIM/64, N_TOK/64, NH);
    sgemm_bias_kernel<<<g1, blk>>>(x, Wq, bq, nullptr, N_TOK, DIM, DIM,
                                   (long)DIM*DIM, DIM, 0, 0);
    sgemm_bias_kernel<<<g1, blk>>>(x, Wk, bk, nullptr, N_TOK, DIM, DIM,
                                   (long)DIM*DIM, DIM, 0, 1);
    sgemm_bias_kernel<<<g1, blk>>>(x, Wv, bv, nullptr, N_TOK, DIM, DIM,
                                   (long)DIM*DIM, DIM, 0, 2);

    dim3 g2(N_TOK/128, NH);
    attn_mma_kernel<<<g2, blk, SMEM_DYN>>>();

    dim3 g3(DIM/64, N_TOK/64, 1);
    sgemm_bias_kernel<<<g3, blk>>>(nullptr, Wo, bo, out, N_TOK, DIM, HD,
                                   0, 0, 1, 3);
}